// round 2
// baseline (speedup 1.0000x reference)
#include <cuda_runtime.h>
#include <cstdint>

#define NMAX 100000
#define EMAX 3200000
#define HID 64
#define INC 11

// Scratch (static __device__ — no allocations allowed)
__device__ __align__(16) float g_agg1[NMAX * 12];   // 11 feature sums + count in slot 11
__device__ __align__(16) float g_h1[NMAX * HID];    // layer-1 output
__device__ __align__(16) float g_agg2[NMAX * HID];  // layer-2 neighbor sums
__device__ int g_src[EMAX];
__device__ int g_dst[EMAX];
__device__ int g_is64;

__device__ __forceinline__ void red4(float* addr, float a, float b, float c, float d) {
    asm volatile("red.global.add.v4.f32 [%0], {%1,%2,%3,%4};"
                 :: "l"(addr), "f"(a), "f"(b), "f"(c), "f"(d) : "memory");
}

// ---------------------------------------------------------------------------
// Probe: decide whether edge_index is int64 or int32 (JAX x64 is usually off,
// so "int64" often arrives as int32). Reading int32 data as int64 yields
// values >= N essentially surely, so this test is reliable.
// ---------------------------------------------------------------------------
__global__ void probe_kernel(const void* ei, int N) {
    const long long* p = (const long long*)ei;
    int ok = 1;
#pragma unroll
    for (int i = 0; i < 16; i++) {
        long long v = p[i];
        if (v < 0 || v >= (long long)N) ok = 0;
    }
    g_is64 = ok;
}

// Materialize int32 src/dst arrays (also halves index traffic downstream).
__global__ void convert_kernel(const void* ei, int E) {
    int i = blockIdx.x * blockDim.x + threadIdx.x;
    if (i >= E) return;
    if (g_is64) {
        const long long* p = (const long long*)ei;
        g_src[i] = (int)p[i];
        g_dst[i] = (int)p[E + i];
    } else {
        const int* p = (const int*)ei;
        g_src[i] = p[i];
        g_dst[i] = p[E + i];
    }
}

// ---------------------------------------------------------------------------
// Zero the accumulators (float4 grid-stride)
// ---------------------------------------------------------------------------
__global__ void zero_kernel(int n1, int n2) {
    int i = blockIdx.x * blockDim.x + threadIdx.x;
    int stride = gridDim.x * blockDim.x;
    float4 z = {0.f, 0.f, 0.f, 0.f};
    int q1 = n1 >> 2, q2 = n2 >> 2;
    for (int j = i; j < q1; j += stride) ((float4*)g_agg1)[j] = z;
    for (int j = i; j < q2; j += stride) ((float4*)g_agg2)[j] = z;
}

// ---------------------------------------------------------------------------
// Layer-1 edge pass: scatter x[src] (11ch) + degree count (lane 11)
// ---------------------------------------------------------------------------
__global__ void edge1_kernel(const float* __restrict__ x, int E) {
    int e = blockIdx.x * blockDim.x + threadIdx.x;
    if (e >= E) return;
    int s = g_src[e];
    int d = g_dst[e];
    const float* xr = x + (size_t)s * INC;
    float v[11];
#pragma unroll
    for (int k = 0; k < 11; k++) v[k] = __ldg(xr + k);
    float* a = g_agg1 + (size_t)d * 12;
    red4(a + 0, v[0], v[1], v[2],  v[3]);
    red4(a + 4, v[4], v[5], v[6],  v[7]);
    red4(a + 8, v[8], v[9], v[10], 1.0f);   // slot 11 accumulates the degree
}

// ---------------------------------------------------------------------------
// Layer-1 node pass: h1 = relu(mean @ Wl1^T + bl1 + x @ Wr1^T)
// 256 threads = 4 nodes x 64 output channels; weights staged in smem.
// ---------------------------------------------------------------------------
__global__ void node1_kernel(const float* __restrict__ x,
                             const float* __restrict__ Wl1,
                             const float* __restrict__ bl1,
                             const float* __restrict__ Wr1, int N) {
    __shared__ float sWl[64 * 11], sWr[64 * 11], sb[64];
    __shared__ float sm[4][12], sx[4][12], sinv[4];
    int tid = threadIdx.x;
    for (int j = tid; j < 64 * 11; j += 256) { sWl[j] = Wl1[j]; sWr[j] = Wr1[j]; }
    if (tid < 64) sb[tid] = bl1[tid];
    int g = tid >> 6, c = tid & 63;
    int n = blockIdx.x * 4 + g;
    __syncthreads();
    if (n < N && c == 0) {
        float cnt = g_agg1[(size_t)n * 12 + 11];
        sinv[g] = 1.0f / fmaxf(cnt, 1.0f);
    }
    __syncthreads();
    if (n < N && c < 11) {
        sx[g][c] = x[(size_t)n * 11 + c];
        sm[g][c] = g_agg1[(size_t)n * 12 + c] * sinv[g];
    }
    __syncthreads();
    if (n < N) {
        float acc = sb[c];
#pragma unroll
        for (int k = 0; k < 11; k++)
            acc += sWl[c * 11 + k] * sm[g][k] + sWr[c * 11 + k] * sx[g][k];
        g_h1[(size_t)n * 64 + c] = fmaxf(acc, 0.0f);
    }
}

// ---------------------------------------------------------------------------
// Layer-2 edge pass: scatter h1[src] (64ch) into agg2[dst].
// 8 threads per edge -> coalesced 256B row gather + 2 red.v4 per thread.
// ---------------------------------------------------------------------------
__global__ void edge2_kernel(int E) {
    long long tid = (long long)blockIdx.x * blockDim.x + threadIdx.x;
    int e = (int)(tid >> 3);
    if (e >= E) return;
    int t8 = (int)(tid & 7);
    int s = g_src[e];
    int d = g_dst[e];
    const float4* srcp = (const float4*)(g_h1 + (size_t)s * 64) + t8 * 2;
    float4 a = __ldg(srcp);
    float4 b = __ldg(srcp + 1);
    float* dstp = g_agg2 + (size_t)d * 64 + t8 * 8;
    red4(dstp + 0, a.x, a.y, a.z, a.w);
    red4(dstp + 4, b.x, b.y, b.z, b.w);
}

// ---------------------------------------------------------------------------
// Layer-2 node pass + final linear, fused:
//   h2 = relu(mean2 @ Wl2^T + bl2 + h1 @ Wr2^T);  out = h2 @ Wlin^T + blin
// 256 threads = 4 groups x 64 channels; each group handles 2 nodes.
// ---------------------------------------------------------------------------
__global__ void node2_kernel(const float* __restrict__ Wl2,
                             const float* __restrict__ bl2,
                             const float* __restrict__ Wr2,
                             const float* __restrict__ Wlin,
                             const float* __restrict__ blin,
                             float* __restrict__ out, int N) {
    __shared__ float sWl[64 * 65], sWr[64 * 65], sb[64], swo[64];
    __shared__ float sm[8][64], sh[8][64];
    __shared__ float sred[8][2];
    int tid = threadIdx.x;
    for (int j = tid; j < 4096; j += 256) {
        int r = j >> 6, k = j & 63;
        sWl[r * 65 + k] = Wl2[j];
        sWr[r * 65 + k] = Wr2[j];
    }
    if (tid < 64) { sb[tid] = bl2[tid]; swo[tid] = Wlin[tid]; }
    int g = tid >> 6, c = tid & 63;
    int n0 = blockIdx.x * 8 + g * 2;
    int n1 = n0 + 1;
    __syncthreads();
    if (n0 < N) {
        float inv = 1.0f / fmaxf(g_agg1[(size_t)n0 * 12 + 11], 1.0f);
        sm[g * 2][c] = g_agg2[(size_t)n0 * 64 + c] * inv;
        sh[g * 2][c] = g_h1[(size_t)n0 * 64 + c];
    }
    if (n1 < N) {
        float inv = 1.0f / fmaxf(g_agg1[(size_t)n1 * 12 + 11], 1.0f);
        sm[g * 2 + 1][c] = g_agg2[(size_t)n1 * 64 + c] * inv;
        sh[g * 2 + 1][c] = g_h1[(size_t)n1 * 64 + c];
    }
    __syncthreads();
    float acc0 = sb[c], acc1 = sb[c];
    const float* m0 = sm[g * 2];
    const float* h0 = sh[g * 2];
    const float* m1 = sm[g * 2 + 1];
    const float* h1r = sh[g * 2 + 1];
#pragma unroll
    for (int k = 0; k < 64; k++) {
        float wl = sWl[c * 65 + k];
        float wr = sWr[c * 65 + k];
        acc0 += wl * m0[k] + wr * h0[k];
        acc1 += wl * m1[k] + wr * h1r[k];
    }
    float p0 = swo[c] * fmaxf(acc0, 0.0f);
    float p1 = swo[c] * fmaxf(acc1, 0.0f);
#pragma unroll
    for (int off = 16; off; off >>= 1) {
        p0 += __shfl_down_sync(0xffffffffu, p0, off);
        p1 += __shfl_down_sync(0xffffffffu, p1, off);
    }
    int lane = c & 31, w = c >> 5;
    if (lane == 0) { sred[g * 2][w] = p0; sred[g * 2 + 1][w] = p1; }
    __syncthreads();
    if (c == 0) {
        float bo = blin[0];
        if (n0 < N) out[n0] = sred[g * 2][0] + sred[g * 2][1] + bo;
        if (n1 < N) out[n1] = sred[g * 2 + 1][0] + sred[g * 2 + 1][1] + bo;
    }
}

// ---------------------------------------------------------------------------
extern "C" void kernel_launch(void* const* d_in, const int* in_sizes, int n_in,
                              void* d_out, int out_size) {
    const float* x    = (const float*)d_in[0];
    const void*  ei   = d_in[1];
    const float* Wl1  = (const float*)d_in[2];
    const float* bl1  = (const float*)d_in[3];
    const float* Wr1  = (const float*)d_in[4];
    const float* Wl2  = (const float*)d_in[5];
    const float* bl2  = (const float*)d_in[6];
    const float* Wr2  = (const float*)d_in[7];
    const float* Wlin = (const float*)d_in[8];
    const float* blin = (const float*)d_in[9];
    float* out = (float*)d_out;

    int N = in_sizes[0] / INC;
    int E = in_sizes[1] / 2;

    probe_kernel<<<1, 1>>>(ei, N);
    convert_kernel<<<(E + 255) / 256, 256>>>(ei, E);
    zero_kernel<<<1024, 256>>>(N * 12, N * HID);
    edge1_kernel<<<(E + 255) / 256, 256>>>(x, E);
    node1_kernel<<<(N + 3) / 4, 256>>>(x, Wl1, bl1, Wr1, N);
    long long t2 = (long long)E * 8;
    edge2_kernel<<<(int)((t2 + 255) / 256), 256>>>(E);
    node2_kernel<<<(N + 7) / 8, 256>>>(Wl2, bl2, Wr2, Wlin, blin, out, N);
}

// round 3
// speedup vs baseline: 1.3311x; 1.3311x over previous
#include <cuda_runtime.h>
#include <cstdint>

#define NMAX 100000
#define EMAX 3200000
#define HID 64
#define INC 11

// ---- static scratch (no allocations allowed) ----
__device__ int g_deg[NMAX];
__device__ int g_off[NMAX];
__device__ int g_pos[NMAX];
__device__ int g_blocksum[256];
__device__ int g_src[EMAX];
__device__ int g_dst[EMAX];
__device__ int g_csr[EMAX];                          // src ids grouped by dst
__device__ __align__(16) float g_agg1[NMAX * 12];    // mean of x over in-neighbors (11 used)
__device__ __align__(16) float g_h1[NMAX * HID];     // layer-1 output
__device__ __align__(16) float g_agg2[NMAX * HID];   // mean of h1 over in-neighbors
__device__ int g_is64;

// ---------------------------------------------------------------------------
// dtype probe: JAX x64 is usually disabled, so "int64" edge_index often
// arrives as int32. Reading int32 data as int64 gives values >= N w.h.p.
// ---------------------------------------------------------------------------
__global__ void probe_kernel(const void* ei, int N) {
    const long long* p = (const long long*)ei;
    int ok = 1;
#pragma unroll
    for (int i = 0; i < 16; i++) {
        long long v = p[i];
        if (v < 0 || v >= (long long)N) ok = 0;
    }
    g_is64 = ok;
}

__global__ void zero_deg_kernel(int N) {
    int i = blockIdx.x * blockDim.x + threadIdx.x;
    if (i < N) g_deg[i] = 0;
}

// Convert indices to int32 + histogram degrees in one pass.
__global__ void convert_kernel(const void* ei, int E) {
    int i = blockIdx.x * blockDim.x + threadIdx.x;
    if (i >= E) return;
    int s, d;
    if (g_is64) {
        const long long* p = (const long long*)ei;
        s = (int)p[i]; d = (int)p[E + i];
    } else {
        const int* p = (const int*)ei;
        s = p[i]; d = p[E + i];
    }
    g_src[i] = s;
    g_dst[i] = d;
    atomicAdd(&g_deg[d], 1);
}

// ---- exclusive prefix scan of g_deg into g_off (3 small kernels) ----
__global__ void scan1_kernel(int N) {
    __shared__ int sh[1024];
    int tid = threadIdx.x;
    int i = blockIdx.x * 1024 + tid;
    int v = (i < N) ? g_deg[i] : 0;
    sh[tid] = v;
    __syncthreads();
    for (int d = 1; d < 1024; d <<= 1) {
        int t = (tid >= d) ? sh[tid - d] : 0;
        __syncthreads();
        sh[tid] += t;
        __syncthreads();
    }
    if (i < N) g_off[i] = sh[tid] - v;          // exclusive
    if (tid == 1023) g_blocksum[blockIdx.x] = sh[1023];
}

__global__ void scan2_kernel(int nb) {
    __shared__ int sh[256];
    int tid = threadIdx.x;
    int v = (tid < nb) ? g_blocksum[tid] : 0;
    sh[tid] = v;
    __syncthreads();
    for (int d = 1; d < 256; d <<= 1) {
        int t = (tid >= d) ? sh[tid - d] : 0;
        __syncthreads();
        sh[tid] += t;
        __syncthreads();
    }
    if (tid < nb) g_blocksum[tid] = sh[tid] - v;  // exclusive block offsets
}

__global__ void scan3_kernel(int N) {
    int i = blockIdx.x * blockDim.x + threadIdx.x;
    if (i >= N) return;
    int o = g_off[i] + g_blocksum[i >> 10];
    g_off[i] = o;
    g_pos[i] = o;
}

// Scatter edges into dst-grouped CSR slots.
__global__ void build_kernel(int E) {
    int e = blockIdx.x * blockDim.x + threadIdx.x;
    if (e >= E) return;
    int d = g_dst[e];
    int slot = atomicAdd(&g_pos[d], 1);
    g_csr[slot] = g_src[e];
}

// ---------------------------------------------------------------------------
// Layer-1 aggregation: warp per node, lane per neighbor. Atomic-free.
// Writes MEAN of x over in-neighbors into g_agg1 (stride 12).
// ---------------------------------------------------------------------------
__global__ void agg1_kernel(const float* __restrict__ x, int N) {
    int gt = blockIdx.x * blockDim.x + threadIdx.x;
    int n = gt >> 5, lane = gt & 31;
    if (n >= N) return;
    int off = g_off[n], deg = g_deg[n];
    float acc[11];
#pragma unroll
    for (int k = 0; k < 11; k++) acc[k] = 0.f;
    for (int j = lane; j < deg; j += 32) {
        int s = g_csr[off + j];
        const float* xr = x + (size_t)s * INC;
#pragma unroll
        for (int k = 0; k < 11; k++) acc[k] += __ldg(xr + k);
    }
#pragma unroll
    for (int k = 0; k < 11; k++) {
#pragma unroll
        for (int m = 16; m; m >>= 1)
            acc[k] += __shfl_xor_sync(0xffffffffu, acc[k], m);
    }
    float inv = 1.0f / fmaxf((float)deg, 1.0f);
    if (lane < 11) {
        float v = 0.f;
#pragma unroll
        for (int k = 0; k < 11; k++) if (lane == k) v = acc[k];
        g_agg1[(size_t)n * 12 + lane] = v * inv;
    }
}

// ---------------------------------------------------------------------------
// Layer-1 node pass: h1 = relu(mean1 @ Wl1^T + bl1 + x @ Wr1^T)
// 256 threads = 4 nodes x 64 output channels; weights staged in smem.
// ---------------------------------------------------------------------------
__global__ void node1_kernel(const float* __restrict__ x,
                             const float* __restrict__ Wl1,
                             const float* __restrict__ bl1,
                             const float* __restrict__ Wr1, int N) {
    __shared__ float sWl[64 * 11], sWr[64 * 11], sb[64];
    __shared__ float sm[4][12], sx[4][12];
    int tid = threadIdx.x;
    for (int j = tid; j < 64 * 11; j += 256) { sWl[j] = Wl1[j]; sWr[j] = Wr1[j]; }
    if (tid < 64) sb[tid] = bl1[tid];
    int g = tid >> 6, c = tid & 63;
    int n = blockIdx.x * 4 + g;
    __syncthreads();
    if (n < N && c < 11) {
        sx[g][c] = x[(size_t)n * 11 + c];
        sm[g][c] = g_agg1[(size_t)n * 12 + c];
    }
    __syncthreads();
    if (n < N) {
        float acc = sb[c];
#pragma unroll
        for (int k = 0; k < 11; k++)
            acc += sWl[c * 11 + k] * sm[g][k] + sWr[c * 11 + k] * sx[g][k];
        g_h1[(size_t)n * 64 + c] = fmaxf(acc, 0.0f);
    }
}

// ---------------------------------------------------------------------------
// Layer-2 aggregation: warp per node, lane holds channels (2l, 2l+1).
// Each neighbor iteration reads one coalesced 256B h1 row. Atomic-free.
// Writes MEAN of h1 into g_agg2.
// ---------------------------------------------------------------------------
__global__ void agg2_kernel(int N) {
    int gt = blockIdx.x * blockDim.x + threadIdx.x;
    int n = gt >> 5, lane = gt & 31;
    if (n >= N) return;
    int off = g_off[n], deg = g_deg[n];
    const float2* h1 = (const float2*)g_h1;
    float ax = 0.f, ay = 0.f;
    int j = 0;
    while (j < deg) {
        int take = deg - j;
        if (take > 32) take = 32;
        int idx = (lane < take) ? g_csr[off + j + lane] : 0;
        for (int t = 0; t < take; t++) {
            int s = __shfl_sync(0xffffffffu, idx, t);
            float2 v = __ldg(&h1[(size_t)s * 32 + lane]);
            ax += v.x; ay += v.y;
        }
        j += take;
    }
    float inv = 1.0f / fmaxf((float)deg, 1.0f);
    ((float2*)g_agg2)[(size_t)n * 32 + lane] = make_float2(ax * inv, ay * inv);
}

// ---------------------------------------------------------------------------
// Layer-2 node pass + final linear, fused:
//   h2 = relu(mean2 @ Wl2^T + bl2 + h1 @ Wr2^T);  out = h2 @ Wlin^T + blin
// 256 threads = 4 groups x 64 channels; each group handles 2 nodes.
// ---------------------------------------------------------------------------
__global__ void node2_kernel(const float* __restrict__ Wl2,
                             const float* __restrict__ bl2,
                             const float* __restrict__ Wr2,
                             const float* __restrict__ Wlin,
                             const float* __restrict__ blin,
                             float* __restrict__ out, int N) {
    __shared__ float sWl[64 * 65], sWr[64 * 65], sb[64], swo[64];
    __shared__ float sm[8][64], sh[8][64];
    __shared__ float sred[8][2];
    int tid = threadIdx.x;
    for (int j = tid; j < 4096; j += 256) {
        int r = j >> 6, k = j & 63;
        sWl[r * 65 + k] = Wl2[j];
        sWr[r * 65 + k] = Wr2[j];
    }
    if (tid < 64) { sb[tid] = bl2[tid]; swo[tid] = Wlin[tid]; }
    int g = tid >> 6, c = tid & 63;
    int n0 = blockIdx.x * 8 + g * 2;
    int n1 = n0 + 1;
    __syncthreads();
    if (n0 < N) {
        sm[g * 2][c] = g_agg2[(size_t)n0 * 64 + c];
        sh[g * 2][c] = g_h1[(size_t)n0 * 64 + c];
    }
    if (n1 < N) {
        sm[g * 2 + 1][c] = g_agg2[(size_t)n1 * 64 + c];
        sh[g * 2 + 1][c] = g_h1[(size_t)n1 * 64 + c];
    }
    __syncthreads();
    float acc0 = sb[c], acc1 = sb[c];
    const float* m0 = sm[g * 2];
    const float* h0 = sh[g * 2];
    const float* m1 = sm[g * 2 + 1];
    const float* h1r = sh[g * 2 + 1];
#pragma unroll
    for (int k = 0; k < 64; k++) {
        float wl = sWl[c * 65 + k];
        float wr = sWr[c * 65 + k];
        acc0 += wl * m0[k] + wr * h0[k];
        acc1 += wl * m1[k] + wr * h1r[k];
    }
    float p0 = swo[c] * fmaxf(acc0, 0.0f);
    float p1 = swo[c] * fmaxf(acc1, 0.0f);
#pragma unroll
    for (int off = 16; off; off >>= 1) {
        p0 += __shfl_down_sync(0xffffffffu, p0, off);
        p1 += __shfl_down_sync(0xffffffffu, p1, off);
    }
    int lane = c & 31, w = c >> 5;
    if (lane == 0) { sred[g * 2][w] = p0; sred[g * 2 + 1][w] = p1; }
    __syncthreads();
    if (c == 0) {
        float bo = blin[0];
        if (n0 < N) out[n0] = sred[g * 2][0] + sred[g * 2][1] + bo;
        if (n1 < N) out[n1] = sred[g * 2 + 1][0] + sred[g * 2 + 1][1] + bo;
    }
}

// ---------------------------------------------------------------------------
extern "C" void kernel_launch(void* const* d_in, const int* in_sizes, int n_in,
                              void* d_out, int out_size) {
    const float* x    = (const float*)d_in[0];
    const void*  ei   = d_in[1];
    const float* Wl1  = (const float*)d_in[2];
    const float* bl1  = (const float*)d_in[3];
    const float* Wr1  = (const float*)d_in[4];
    const float* Wl2  = (const float*)d_in[5];
    const float* bl2  = (const float*)d_in[6];
    const float* Wr2  = (const float*)d_in[7];
    const float* Wlin = (const float*)d_in[8];
    const float* blin = (const float*)d_in[9];
    float* out = (float*)d_out;

    int N = in_sizes[0] / INC;
    int E = in_sizes[1] / 2;
    int nb = (N + 1023) / 1024;

    probe_kernel<<<1, 1>>>(ei, N);
    zero_deg_kernel<<<(N + 255) / 256, 256>>>(N);
    convert_kernel<<<(E + 255) / 256, 256>>>(ei, E);
    scan1_kernel<<<nb, 1024>>>(N);
    scan2_kernel<<<1, 256>>>(nb);
    scan3_kernel<<<(N + 255) / 256, 256>>>(N);
    build_kernel<<<(E + 255) / 256, 256>>>(E);

    long long t1 = (long long)N * 32;
    agg1_kernel<<<(int)((t1 + 255) / 256), 256>>>(x, N);
    node1_kernel<<<(N + 3) / 4, 256>>>(x, Wl1, bl1, Wr1, N);
    agg2_kernel<<<(int)((t1 + 255) / 256), 256>>>(N);
    node2_kernel<<<(N + 7) / 8, 256>>>(Wl2, bl2, Wr2, Wlin, blin, out, N);
}

// round 4
// speedup vs baseline: 1.3652x; 1.0257x over previous
#include <cuda_runtime.h>
#include <cuda_fp16.h>
#include <cstdint>

#define NMAX 100000
#define EMAX 3200000
#define HID 64
#define INC 11

// ---- static scratch (no allocations allowed) ----
__device__ int g_deg[NMAX];
__device__ int g_off[NMAX];
__device__ int g_pos[NMAX];
__device__ int g_blocksum[256];
__device__ int g_src[EMAX];
__device__ int g_dst[EMAX];
__device__ int g_csr[EMAX];                           // src ids grouped by dst
__device__ __align__(16) float g_agg1[NMAX * 12];     // mean of x (11 used)
__device__ __align__(16) float g_h1[NMAX * HID];      // layer-1 output fp32
__device__ __align__(16) __half2 g_h1h[NMAX * 32];    // layer-1 output fp16 mirror
__device__ __align__(16) float g_agg2[NMAX * HID];    // mean of h1
__device__ int g_is64;

// ---------------------------------------------------------------------------
// dtype probe: JAX x64 is usually disabled, so "int64" edge_index often
// arrives as int32. Reading int32 data as int64 gives values >= N w.h.p.
// ---------------------------------------------------------------------------
__global__ void probe_kernel(const void* ei, int N) {
    const long long* p = (const long long*)ei;
    int ok = 1;
#pragma unroll
    for (int i = 0; i < 16; i++) {
        long long v = p[i];
        if (v < 0 || v >= (long long)N) ok = 0;
    }
    g_is64 = ok;
}

__global__ void zero_deg_kernel(int N) {
    int i = blockIdx.x * blockDim.x + threadIdx.x;
    if (i < N) g_deg[i] = 0;
}

// Convert indices to int32 + histogram degrees in one pass.
__global__ void convert_kernel(const void* ei, int E) {
    int i = blockIdx.x * blockDim.x + threadIdx.x;
    if (i >= E) return;
    int s, d;
    if (g_is64) {
        const long long* p = (const long long*)ei;
        s = (int)p[i]; d = (int)p[E + i];
    } else {
        const int* p = (const int*)ei;
        s = p[i]; d = p[E + i];
    }
    g_src[i] = s;
    g_dst[i] = d;
    atomicAdd(&g_deg[d], 1);
}

// ---- exclusive prefix scan of g_deg into g_off ----
__global__ void scan1_kernel(int N) {
    __shared__ int sh[1024];
    int tid = threadIdx.x;
    int i = blockIdx.x * 1024 + tid;
    int v = (i < N) ? g_deg[i] : 0;
    sh[tid] = v;
    __syncthreads();
    for (int d = 1; d < 1024; d <<= 1) {
        int t = (tid >= d) ? sh[tid - d] : 0;
        __syncthreads();
        sh[tid] += t;
        __syncthreads();
    }
    if (i < N) g_off[i] = sh[tid] - v;          // exclusive
    if (tid == 1023) g_blocksum[blockIdx.x] = sh[1023];
}

__global__ void scan2_kernel(int nb) {
    __shared__ int sh[256];
    int tid = threadIdx.x;
    int v = (tid < nb) ? g_blocksum[tid] : 0;
    sh[tid] = v;
    __syncthreads();
    for (int d = 1; d < 256; d <<= 1) {
        int t = (tid >= d) ? sh[tid - d] : 0;
        __syncthreads();
        sh[tid] += t;
        __syncthreads();
    }
    if (tid < nb) g_blocksum[tid] = sh[tid] - v;
}

__global__ void scan3_kernel(int N) {
    int i = blockIdx.x * blockDim.x + threadIdx.x;
    if (i >= N) return;
    int o = g_off[i] + g_blocksum[i >> 10];
    g_off[i] = o;
    g_pos[i] = o;
}

// Scatter edges into dst-grouped CSR slots.
__global__ void build_kernel(int E) {
    int e = blockIdx.x * blockDim.x + threadIdx.x;
    if (e >= E) return;
    int d = g_dst[e];
    int slot = atomicAdd(&g_pos[d], 1);
    g_csr[slot] = g_src[e];
}

// ---------------------------------------------------------------------------
// Layer-1 aggregation: warp per node, lane per neighbor. Atomic-free.
// ---------------------------------------------------------------------------
__global__ void agg1_kernel(const float* __restrict__ x, int N) {
    int gt = blockIdx.x * blockDim.x + threadIdx.x;
    int n = gt >> 5, lane = gt & 31;
    if (n >= N) return;
    int off = g_off[n], deg = g_deg[n];
    float acc[11];
#pragma unroll
    for (int k = 0; k < 11; k++) acc[k] = 0.f;
    for (int j = lane; j < deg; j += 32) {
        int s = g_csr[off + j];
        const float* xr = x + (size_t)s * INC;
#pragma unroll
        for (int k = 0; k < 11; k++) acc[k] += __ldg(xr + k);
    }
#pragma unroll
    for (int k = 0; k < 11; k++) {
#pragma unroll
        for (int m = 16; m; m >>= 1)
            acc[k] += __shfl_xor_sync(0xffffffffu, acc[k], m);
    }
    float inv = 1.0f / fmaxf((float)deg, 1.0f);
    if (lane < 11) {
        float v = 0.f;
#pragma unroll
        for (int k = 0; k < 11; k++) if (lane == k) v = acc[k];
        g_agg1[(size_t)n * 12 + lane] = v * inv;
    }
}

// ---------------------------------------------------------------------------
// Layer-1 node pass: h1 = relu(mean1 @ Wl1^T + bl1 + x @ Wr1^T)
// Writes fp32 h1 (for node2) and fp16 mirror (for the big gather).
// ---------------------------------------------------------------------------
__global__ void node1_kernel(const float* __restrict__ x,
                             const float* __restrict__ Wl1,
                             const float* __restrict__ bl1,
                             const float* __restrict__ Wr1, int N) {
    __shared__ float sWl[64 * 11], sWr[64 * 11], sb[64];
    __shared__ float sm[4][12], sx[4][12];
    __shared__ float sh1[4][64];
    int tid = threadIdx.x;
    for (int j = tid; j < 64 * 11; j += 256) { sWl[j] = Wl1[j]; sWr[j] = Wr1[j]; }
    if (tid < 64) sb[tid] = bl1[tid];
    int g = tid >> 6, c = tid & 63;
    int n = blockIdx.x * 4 + g;
    __syncthreads();
    if (n < N && c < 11) {
        sx[g][c] = x[(size_t)n * 11 + c];
        sm[g][c] = g_agg1[(size_t)n * 12 + c];
    }
    __syncthreads();
    if (n < N) {
        float acc = sb[c];
#pragma unroll
        for (int k = 0; k < 11; k++)
            acc += sWl[c * 11 + k] * sm[g][k] + sWr[c * 11 + k] * sx[g][k];
        float r = fmaxf(acc, 0.0f);
        g_h1[(size_t)n * 64 + c] = r;
        sh1[g][c] = r;
    }
    __syncthreads();
    // fp16 mirror: lanes 0..31 of each group pack channel pairs
    if (n < N && c < 32)
        g_h1h[(size_t)n * 32 + c] =
            __floats2half2_rn(sh1[g][c * 2], sh1[g][c * 2 + 1]);
}

// ---------------------------------------------------------------------------
// Layer-2 aggregation: warp per node, lane holds channels (2l, 2l+1).
// fp16 rows (128B), unroll x8 for MLP, uniform index loads. Atomic-free.
// ---------------------------------------------------------------------------
__global__ void agg2_kernel(int N) {
    int gt = blockIdx.x * blockDim.x + threadIdx.x;
    int n = gt >> 5, lane = gt & 31;
    if (n >= N) return;
    int off = g_off[n], deg = g_deg[n];
    const __half2* h1 = g_h1h;
    const int* __restrict__ csr = g_csr + off;
    float ax = 0.f, ay = 0.f;
    int j = 0;
    for (; j + 8 <= deg; j += 8) {
        int s0 = csr[j + 0], s1 = csr[j + 1], s2 = csr[j + 2], s3 = csr[j + 3];
        int s4 = csr[j + 4], s5 = csr[j + 5], s6 = csr[j + 6], s7 = csr[j + 7];
        __half2 v0 = __ldg(&h1[(size_t)s0 * 32 + lane]);
        __half2 v1 = __ldg(&h1[(size_t)s1 * 32 + lane]);
        __half2 v2 = __ldg(&h1[(size_t)s2 * 32 + lane]);
        __half2 v3 = __ldg(&h1[(size_t)s3 * 32 + lane]);
        __half2 v4 = __ldg(&h1[(size_t)s4 * 32 + lane]);
        __half2 v5 = __ldg(&h1[(size_t)s5 * 32 + lane]);
        __half2 v6 = __ldg(&h1[(size_t)s6 * 32 + lane]);
        __half2 v7 = __ldg(&h1[(size_t)s7 * 32 + lane]);
        float2 f0 = __half22float2(v0), f1 = __half22float2(v1);
        float2 f2 = __half22float2(v2), f3 = __half22float2(v3);
        float2 f4 = __half22float2(v4), f5 = __half22float2(v5);
        float2 f6 = __half22float2(v6), f7 = __half22float2(v7);
        ax += (f0.x + f1.x) + (f2.x + f3.x) + (f4.x + f5.x) + (f6.x + f7.x);
        ay += (f0.y + f1.y) + (f2.y + f3.y) + (f4.y + f5.y) + (f6.y + f7.y);
    }
    for (; j < deg; j++) {
        int s = csr[j];
        float2 f = __half22float2(__ldg(&h1[(size_t)s * 32 + lane]));
        ax += f.x; ay += f.y;
    }
    float inv = 1.0f / fmaxf((float)deg, 1.0f);
    ((float2*)g_agg2)[(size_t)n * 32 + lane] = make_float2(ax * inv, ay * inv);
}

// ---------------------------------------------------------------------------
// Layer-2 node pass + final linear, fused.
// ---------------------------------------------------------------------------
__global__ void node2_kernel(const float* __restrict__ Wl2,
                             const float* __restrict__ bl2,
                             const float* __restrict__ Wr2,
                             const float* __restrict__ Wlin,
                             const float* __restrict__ blin,
                             float* __restrict__ out, int N) {
    __shared__ float sWl[64 * 65], sWr[64 * 65], sb[64], swo[64];
    __shared__ float sm[8][64], sh[8][64];
    __shared__ float sred[8][2];
    int tid = threadIdx.x;
    for (int j = tid; j < 4096; j += 256) {
        int r = j >> 6, k = j & 63;
        sWl[r * 65 + k] = Wl2[j];
        sWr[r * 65 + k] = Wr2[j];
    }
    if (tid < 64) { sb[tid] = bl2[tid]; swo[tid] = Wlin[tid]; }
    int g = tid >> 6, c = tid & 63;
    int n0 = blockIdx.x * 8 + g * 2;
    int n1 = n0 + 1;
    __syncthreads();
    if (n0 < N) {
        sm[g * 2][c] = g_agg2[(size_t)n0 * 64 + c];
        sh[g * 2][c] = g_h1[(size_t)n0 * 64 + c];
    }
    if (n1 < N) {
        sm[g * 2 + 1][c] = g_agg2[(size_t)n1 * 64 + c];
        sh[g * 2 + 1][c] = g_h1[(size_t)n1 * 64 + c];
    }
    __syncthreads();
    float acc0 = sb[c], acc1 = sb[c];
    const float* m0 = sm[g * 2];
    const float* h0 = sh[g * 2];
    const float* m1 = sm[g * 2 + 1];
    const float* h1r = sh[g * 2 + 1];
#pragma unroll
    for (int k = 0; k < 64; k++) {
        float wl = sWl[c * 65 + k];
        float wr = sWr[c * 65 + k];
        acc0 += wl * m0[k] + wr * h0[k];
        acc1 += wl * m1[k] + wr * h1r[k];
    }
    float p0 = swo[c] * fmaxf(acc0, 0.0f);
    float p1 = swo[c] * fmaxf(acc1, 0.0f);
#pragma unroll
    for (int off = 16; off; off >>= 1) {
        p0 += __shfl_down_sync(0xffffffffu, p0, off);
        p1 += __shfl_down_sync(0xffffffffu, p1, off);
    }
    int lane = c & 31, w = c >> 5;
    if (lane == 0) { sred[g * 2][w] = p0; sred[g * 2 + 1][w] = p1; }
    __syncthreads();
    if (c == 0) {
        float bo = blin[0];
        if (n0 < N) out[n0] = sred[g * 2][0] + sred[g * 2][1] + bo;
        if (n1 < N) out[n1] = sred[g * 2 + 1][0] + sred[g * 2 + 1][1] + bo;
    }
}

// ---------------------------------------------------------------------------
extern "C" void kernel_launch(void* const* d_in, const int* in_sizes, int n_in,
                              void* d_out, int out_size) {
    const float* x    = (const float*)d_in[0];
    const void*  ei   = d_in[1];
    const float* Wl1  = (const float*)d_in[2];
    const float* bl1  = (const float*)d_in[3];
    const float* Wr1  = (const float*)d_in[4];
    const float* Wl2  = (const float*)d_in[5];
    const float* bl2  = (const float*)d_in[6];
    const float* Wr2  = (const float*)d_in[7];
    const float* Wlin = (const float*)d_in[8];
    const float* blin = (const float*)d_in[9];
    float* out = (float*)d_out;

    int N = in_sizes[0] / INC;
    int E = in_sizes[1] / 2;
    int nb = (N + 1023) / 1024;

    probe_kernel<<<1, 1>>>(ei, N);
    zero_deg_kernel<<<(N + 255) / 256, 256>>>(N);
    convert_kernel<<<(E + 255) / 256, 256>>>(ei, E);
    scan1_kernel<<<nb, 1024>>>(N);
    scan2_kernel<<<1, 256>>>(nb);
    scan3_kernel<<<(N + 255) / 256, 256>>>(N);
    build_kernel<<<(E + 255) / 256, 256>>>(E);

    long long t1 = (long long)N * 32;
    agg1_kernel<<<(int)((t1 + 255) / 256), 256>>>(x, N);
    node1_kernel<<<(N + 3) / 4, 256>>>(x, Wl1, bl1, Wr1, N);
    agg2_kernel<<<(int)((t1 + 255) / 256), 256>>>(N);
    node2_kernel<<<(N + 7) / 8, 256>>>(Wl2, bl2, Wr2, Wlin, blin, out, N);
}

// round 5
// speedup vs baseline: 1.4305x; 1.0478x over previous
#include <cuda_runtime.h>
#include <cuda_fp16.h>
#include <cstdint>

#define NMAX 100000
#define EMAX 3200000
#define HID 64
#define INC 11

// ---- static scratch (no allocations allowed) ----
__device__ int g_deg[NMAX];
__device__ int g_off[NMAX];
__device__ int g_pos[NMAX];
__device__ int g_blocksum[256];
__device__ int g_src[EMAX];
__device__ int g_dst[EMAX];
__device__ int g_csr[EMAX];                           // src ids grouped by dst
__device__ __align__(32) uint32_t g_xh[NMAX * 8];     // fp16-packed x rows (32B each)
__device__ __align__(16) float g_agg1[NMAX * 12];     // mean of x (11 used)
__device__ __align__(16) float g_h1[NMAX * HID];      // layer-1 output fp32
__device__ __align__(16) __half2 g_h1h[NMAX * 32];    // layer-1 output fp16 mirror
__device__ __align__(16) float g_agg2[NMAX * HID];    // mean of h1
__device__ int g_is64;

// ---------------------------------------------------------------------------
// probe + zero g_deg in one launch. JAX x64 is usually disabled, so "int64"
// edge_index often arrives as int32; reading int32 data as int64 gives
// values >= N w.h.p., which this detects.
// ---------------------------------------------------------------------------
__global__ void probe_zero_kernel(const void* ei, int N) {
    int i = blockIdx.x * blockDim.x + threadIdx.x;
    if (i < N) g_deg[i] = 0;
    if (i == 0) {
        const long long* p = (const long long*)ei;
        int ok = 1;
#pragma unroll
        for (int k = 0; k < 16; k++) {
            long long v = p[k];
            if (v < 0 || v >= (long long)N) ok = 0;
        }
        g_is64 = ok;
    }
}

// Convert indices to int32 + histogram degrees in one pass.
__global__ void convert_kernel(const void* ei, int E) {
    int i = blockIdx.x * blockDim.x + threadIdx.x;
    if (i >= E) return;
    int s, d;
    if (g_is64) {
        const long long* p = (const long long*)ei;
        s = (int)p[i]; d = (int)p[E + i];
    } else {
        const int* p = (const int*)ei;
        s = p[i]; d = p[E + i];
    }
    g_src[i] = s;
    g_dst[i] = d;
    atomicAdd(&g_deg[d], 1);
}

// Pack x rows into fp16, 32B-aligned (16 halfs: 11 channels + zero pad).
__global__ void xpack_kernel(const float* __restrict__ x, int N) {
    int n = blockIdx.x * blockDim.x + threadIdx.x;
    if (n >= N) return;
    const float* xr = x + (size_t)n * INC;
    float v[12];
#pragma unroll
    for (int k = 0; k < 11; k++) v[k] = xr[k];
    v[11] = 0.f;
    uint32_t* o = g_xh + (size_t)n * 8;
#pragma unroll
    for (int k = 0; k < 6; k++) {
        __half2 h = __floats2half2_rn(v[2 * k], v[2 * k + 1]);
        o[k] = *(uint32_t*)&h;
    }
    o[6] = 0u; o[7] = 0u;
}

// ---- exclusive prefix scan of g_deg into g_off ----
__global__ void scan1_kernel(int N) {
    __shared__ int sh[1024];
    int tid = threadIdx.x;
    int i = blockIdx.x * 1024 + tid;
    int v = (i < N) ? g_deg[i] : 0;
    sh[tid] = v;
    __syncthreads();
    for (int d = 1; d < 1024; d <<= 1) {
        int t = (tid >= d) ? sh[tid - d] : 0;
        __syncthreads();
        sh[tid] += t;
        __syncthreads();
    }
    if (i < N) g_off[i] = sh[tid] - v;          // exclusive
    if (tid == 1023) g_blocksum[blockIdx.x] = sh[1023];
}

__global__ void scan2_kernel(int nb) {
    __shared__ int sh[256];
    int tid = threadIdx.x;
    int v = (tid < nb) ? g_blocksum[tid] : 0;
    sh[tid] = v;
    __syncthreads();
    for (int d = 1; d < 256; d <<= 1) {
        int t = (tid >= d) ? sh[tid - d] : 0;
        __syncthreads();
        sh[tid] += t;
        __syncthreads();
    }
    if (tid < nb) g_blocksum[tid] = sh[tid] - v;
}

__global__ void scan3_kernel(int N) {
    int i = blockIdx.x * blockDim.x + threadIdx.x;
    if (i >= N) return;
    int o = g_off[i] + g_blocksum[i >> 10];
    g_off[i] = o;
    g_pos[i] = o;
}

// Scatter edges into dst-grouped CSR slots.
__global__ void build_kernel(int E) {
    int e = blockIdx.x * blockDim.x + threadIdx.x;
    if (e >= E) return;
    int d = g_dst[e];
    int slot = atomicAdd(&g_pos[d], 1);
    g_csr[slot] = g_src[e];
}

// ---------------------------------------------------------------------------
// Layer-1 aggregation: warp per node; lanes = 4 neighbor-slots x 8 channel
// slots. One LDG.32 per lane per step -> 1 sector (1 wavefront) per neighbor
// row. Cross-slot shfl reduction, 6 lanes write float2 means.
// ---------------------------------------------------------------------------
__global__ void agg1_kernel(int N) {
    int gt = blockIdx.x * blockDim.x + threadIdx.x;
    int n = gt >> 5, lane = gt & 31;
    if (n >= N) return;
    int off = g_off[n], deg = g_deg[n];
    int q = lane >> 3, r = lane & 7;
    const uint32_t* __restrict__ csr = (const uint32_t*)(g_csr + off);
    float ax = 0.f, ay = 0.f;
    int j = 0;
#pragma unroll 2
    for (; j + 4 <= deg; j += 4) {
        int s = csr[j + q];
        uint32_t u = __ldg(&g_xh[(size_t)s * 8 + r]);
        float2 f = __half22float2(*(__half2*)&u);
        ax += f.x; ay += f.y;
    }
    if (j + q < deg) {
        int s = csr[j + q];
        uint32_t u = __ldg(&g_xh[(size_t)s * 8 + r]);
        float2 f = __half22float2(*(__half2*)&u);
        ax += f.x; ay += f.y;
    }
    ax += __shfl_xor_sync(0xffffffffu, ax, 8);
    ay += __shfl_xor_sync(0xffffffffu, ay, 8);
    ax += __shfl_xor_sync(0xffffffffu, ax, 16);
    ay += __shfl_xor_sync(0xffffffffu, ay, 16);
    float inv = 1.0f / fmaxf((float)deg, 1.0f);
    if (lane < 6)
        ((float2*)g_agg1)[(size_t)n * 6 + lane] = make_float2(ax * inv, ay * inv);
}

// ---------------------------------------------------------------------------
// Layer-1 node pass: h1 = relu(mean1 @ Wl1^T + bl1 + x @ Wr1^T)
// Writes fp32 h1 (for node2) and fp16 mirror (for the big gather).
// ---------------------------------------------------------------------------
__global__ void node1_kernel(const float* __restrict__ x,
                             const float* __restrict__ Wl1,
                             const float* __restrict__ bl1,
                             const float* __restrict__ Wr1, int N) {
    __shared__ float sWl[64 * 11], sWr[64 * 11], sb[64];
    __shared__ float sm[4][12], sx[4][12];
    __shared__ float sh1[4][64];
    int tid = threadIdx.x;
    for (int j = tid; j < 64 * 11; j += 256) { sWl[j] = Wl1[j]; sWr[j] = Wr1[j]; }
    if (tid < 64) sb[tid] = bl1[tid];
    int g = tid >> 6, c = tid & 63;
    int n = blockIdx.x * 4 + g;
    __syncthreads();
    if (n < N && c < 11) {
        sx[g][c] = x[(size_t)n * 11 + c];
        sm[g][c] = g_agg1[(size_t)n * 12 + c];
    }
    __syncthreads();
    if (n < N) {
        float acc = sb[c];
#pragma unroll
        for (int k = 0; k < 11; k++)
            acc += sWl[c * 11 + k] * sm[g][k] + sWr[c * 11 + k] * sx[g][k];
        float r = fmaxf(acc, 0.0f);
        g_h1[(size_t)n * 64 + c] = r;
        sh1[g][c] = r;
    }
    __syncthreads();
    if (n < N && c < 32)
        g_h1h[(size_t)n * 32 + c] =
            __floats2half2_rn(sh1[g][c * 2], sh1[g][c * 2 + 1]);
}

// ---------------------------------------------------------------------------
// Layer-2 aggregation: warp per node, lane holds channels (2l, 2l+1).
// fp16 rows (128B = 4 sectors), unroll x8 for MLP. Atomic-free.
// ---------------------------------------------------------------------------
__global__ void agg2_kernel(int N) {
    int gt = blockIdx.x * blockDim.x + threadIdx.x;
    int n = gt >> 5, lane = gt & 31;
    if (n >= N) return;
    int off = g_off[n], deg = g_deg[n];
    const __half2* h1 = g_h1h;
    const int* __restrict__ csr = g_csr + off;
    float ax = 0.f, ay = 0.f;
    int j = 0;
    for (; j + 8 <= deg; j += 8) {
        int s0 = csr[j + 0], s1 = csr[j + 1], s2 = csr[j + 2], s3 = csr[j + 3];
        int s4 = csr[j + 4], s5 = csr[j + 5], s6 = csr[j + 6], s7 = csr[j + 7];
        __half2 v0 = __ldg(&h1[(size_t)s0 * 32 + lane]);
        __half2 v1 = __ldg(&h1[(size_t)s1 * 32 + lane]);
        __half2 v2 = __ldg(&h1[(size_t)s2 * 32 + lane]);
        __half2 v3 = __ldg(&h1[(size_t)s3 * 32 + lane]);
        __half2 v4 = __ldg(&h1[(size_t)s4 * 32 + lane]);
        __half2 v5 = __ldg(&h1[(size_t)s5 * 32 + lane]);
        __half2 v6 = __ldg(&h1[(size_t)s6 * 32 + lane]);
        __half2 v7 = __ldg(&h1[(size_t)s7 * 32 + lane]);
        float2 f0 = __half22float2(v0), f1 = __half22float2(v1);
        float2 f2 = __half22float2(v2), f3 = __half22float2(v3);
        float2 f4 = __half22float2(v4), f5 = __half22float2(v5);
        float2 f6 = __half22float2(v6), f7 = __half22float2(v7);
        ax += (f0.x + f1.x) + (f2.x + f3.x) + (f4.x + f5.x) + (f6.x + f7.x);
        ay += (f0.y + f1.y) + (f2.y + f3.y) + (f4.y + f5.y) + (f6.y + f7.y);
    }
    for (; j < deg; j++) {
        int s = csr[j];
        float2 f = __half22float2(__ldg(&h1[(size_t)s * 32 + lane]));
        ax += f.x; ay += f.y;
    }
    float inv = 1.0f / fmaxf((float)deg, 1.0f);
    ((float2*)g_agg2)[(size_t)n * 32 + lane] = make_float2(ax * inv, ay * inv);
}

// ---------------------------------------------------------------------------
// Layer-2 node pass + final linear, fused.
// ---------------------------------------------------------------------------
__global__ void node2_kernel(const float* __restrict__ Wl2,
                             const float* __restrict__ bl2,
                             const float* __restrict__ Wr2,
                             const float* __restrict__ Wlin,
                             const float* __restrict__ blin,
                             float* __restrict__ out, int N) {
    __shared__ float sWl[64 * 65], sWr[64 * 65], sb[64], swo[64];
    __shared__ float sm[8][64], sh[8][64];
    __shared__ float sred[8][2];
    int tid = threadIdx.x;
    for (int j = tid; j < 4096; j += 256) {
        int r = j >> 6, k = j & 63;
        sWl[r * 65 + k] = Wl2[j];
        sWr[r * 65 + k] = Wr2[j];
    }
    if (tid < 64) { sb[tid] = bl2[tid]; swo[tid] = Wlin[tid]; }
    int g = tid >> 6, c = tid & 63;
    int n0 = blockIdx.x * 8 + g * 2;
    int n1 = n0 + 1;
    __syncthreads();
    if (n0 < N) {
        sm[g * 2][c] = g_agg2[(size_t)n0 * 64 + c];
        sh[g * 2][c] = g_h1[(size_t)n0 * 64 + c];
    }
    if (n1 < N) {
        sm[g * 2 + 1][c] = g_agg2[(size_t)n1 * 64 + c];
        sh[g * 2 + 1][c] = g_h1[(size_t)n1 * 64 + c];
    }
    __syncthreads();
    float acc0 = sb[c], acc1 = sb[c];
    const float* m0 = sm[g * 2];
    const float* h0 = sh[g * 2];
    const float* m1 = sm[g * 2 + 1];
    const float* h1r = sh[g * 2 + 1];
#pragma unroll
    for (int k = 0; k < 64; k++) {
        float wl = sWl[c * 65 + k];
        float wr = sWr[c * 65 + k];
        acc0 += wl * m0[k] + wr * h0[k];
        acc1 += wl * m1[k] + wr * h1r[k];
    }
    float p0 = swo[c] * fmaxf(acc0, 0.0f);
    float p1 = swo[c] * fmaxf(acc1, 0.0f);
#pragma unroll
    for (int off = 16; off; off >>= 1) {
        p0 += __shfl_down_sync(0xffffffffu, p0, off);
        p1 += __shfl_down_sync(0xffffffffu, p1, off);
    }
    int lane = c & 31, w = c >> 5;
    if (lane == 0) { sred[g * 2][w] = p0; sred[g * 2 + 1][w] = p1; }
    __syncthreads();
    if (c == 0) {
        float bo = blin[0];
        if (n0 < N) out[n0] = sred[g * 2][0] + sred[g * 2][1] + bo;
        if (n1 < N) out[n1] = sred[g * 2 + 1][0] + sred[g * 2 + 1][1] + bo;
    }
}

// ---------------------------------------------------------------------------
extern "C" void kernel_launch(void* const* d_in, const int* in_sizes, int n_in,
                              void* d_out, int out_size) {
    const float* x    = (const float*)d_in[0];
    const void*  ei   = d_in[1];
    const float* Wl1  = (const float*)d_in[2];
    const float* bl1  = (const float*)d_in[3];
    const float* Wr1  = (const float*)d_in[4];
    const float* Wl2  = (const float*)d_in[5];
    const float* bl2  = (const float*)d_in[6];
    const float* Wr2  = (const float*)d_in[7];
    const float* Wlin = (const float*)d_in[8];
    const float* blin = (const float*)d_in[9];
    float* out = (float*)d_out;

    int N = in_sizes[0] / INC;
    int E = in_sizes[1] / 2;
    int nb = (N + 1023) / 1024;

    probe_zero_kernel<<<(N + 255) / 256, 256>>>(ei, N);
    convert_kernel<<<(E + 255) / 256, 256>>>(ei, E);
    xpack_kernel<<<(N + 255) / 256, 256>>>(x, N);
    scan1_kernel<<<nb, 1024>>>(N);
    scan2_kernel<<<1, 256>>>(nb);
    scan3_kernel<<<(N + 255) / 256, 256>>>(N);
    build_kernel<<<(E + 255) / 256, 256>>>(E);

    long long t1 = (long long)N * 32;
    agg1_kernel<<<(int)((t1 + 255) / 256), 256>>>(N);
    node1_kernel<<<(N + 3) / 4, 256>>>(x, Wl1, bl1, Wr1, N);
    agg2_kernel<<<(int)((t1 + 255) / 256), 256>>>(N);
    node2_kernel<<<(N + 7) / 8, 256>>>(Wl2, bl2, Wr2, Wlin, blin, out, N);
}

// round 6
// speedup vs baseline: 2.0336x; 1.4216x over previous
#include <cuda_runtime.h>
#include <cuda_fp16.h>
#include <cstdint>

#define NMAX 100000
#define EMAX 3200000
#define HID 64
#define INC 11

// ---- static scratch (no allocations allowed) ----
__device__ int g_deg[NMAX];
__device__ int g_off[NMAX];
__device__ int g_pos[NMAX];
__device__ int g_blocksum[256];
__device__ int g_src[EMAX];
__device__ int g_dst[EMAX];
__device__ int g_csr[EMAX];                           // src ids grouped by dst
__device__ __align__(32) uint32_t g_xh[NMAX * 8];     // fp16-packed x rows (32B each)
__device__ __align__(16) float g_agg1[NMAX * 12];     // mean of x (11 used + pad)
__device__ __align__(16) float g_h1[NMAX * HID];      // layer-1 output fp32
__device__ __align__(16) __half2 g_h1h[NMAX * 32];    // layer-1 output fp16 mirror
__device__ __align__(16) float g_agg2[NMAX * HID];    // mean of h1
__device__ int g_is64;

// ---------------------------------------------------------------------------
// probe dtype + zero g_deg + pack x rows to fp16 (one launch).
// JAX x64 is usually disabled, so "int64" edge_index often arrives as int32;
// reading int32 data as int64 gives values >= N w.h.p., which this detects.
// ---------------------------------------------------------------------------
__global__ void prep_kernel(const void* ei, const float* __restrict__ x, int N) {
    int i = blockIdx.x * blockDim.x + threadIdx.x;
    if (i == 0) {
        const long long* p = (const long long*)ei;
        int ok = 1;
#pragma unroll
        for (int k = 0; k < 16; k++) {
            long long v = p[k];
            if (v < 0 || v >= (long long)N) ok = 0;
        }
        g_is64 = ok;
    }
    if (i >= N) return;
    g_deg[i] = 0;
    const float* xr = x + (size_t)i * INC;
    float v[12];
#pragma unroll
    for (int k = 0; k < 11; k++) v[k] = xr[k];
    v[11] = 0.f;
    uint32_t* o = g_xh + (size_t)i * 8;
#pragma unroll
    for (int k = 0; k < 6; k++) {
        __half2 h = __floats2half2_rn(v[2 * k], v[2 * k + 1]);
        o[k] = *(uint32_t*)&h;
    }
    o[6] = 0u; o[7] = 0u;
}

// Convert indices to int32 + histogram degrees in one pass.
__global__ void convert_kernel(const void* ei, int E) {
    int i = blockIdx.x * blockDim.x + threadIdx.x;
    if (i >= E) return;
    int s, d;
    if (g_is64) {
        const long long* p = (const long long*)ei;
        s = (int)p[i]; d = (int)p[E + i];
    } else {
        const int* p = (const int*)ei;
        s = p[i]; d = p[E + i];
    }
    g_src[i] = s;
    g_dst[i] = d;
    atomicAdd(&g_deg[d], 1);
}

// ---- exclusive prefix scan of g_deg into g_off ----
__global__ void scan1_kernel(int N) {
    __shared__ int sh[1024];
    int tid = threadIdx.x;
    int i = blockIdx.x * 1024 + tid;
    int v = (i < N) ? g_deg[i] : 0;
    sh[tid] = v;
    __syncthreads();
    for (int d = 1; d < 1024; d <<= 1) {
        int t = (tid >= d) ? sh[tid - d] : 0;
        __syncthreads();
        sh[tid] += t;
        __syncthreads();
    }
    if (i < N) g_off[i] = sh[tid] - v;          // exclusive
    if (tid == 1023) g_blocksum[blockIdx.x] = sh[1023];
}

__global__ void scan2_kernel(int nb) {
    __shared__ int sh[256];
    int tid = threadIdx.x;
    int v = (tid < nb) ? g_blocksum[tid] : 0;
    sh[tid] = v;
    __syncthreads();
    for (int d = 1; d < 256; d <<= 1) {
        int t = (tid >= d) ? sh[tid - d] : 0;
        __syncthreads();
        sh[tid] += t;
        __syncthreads();
    }
    if (tid < nb) g_blocksum[tid] = sh[tid] - v;
}

__global__ void scan3_kernel(int N) {
    int i = blockIdx.x * blockDim.x + threadIdx.x;
    if (i >= N) return;
    int o = g_off[i] + g_blocksum[i >> 10];
    g_off[i] = o;
    g_pos[i] = o;
}

// Scatter edges into dst-grouped CSR slots.
__global__ void build_kernel(int E) {
    int e = blockIdx.x * blockDim.x + threadIdx.x;
    if (e >= E) return;
    int d = g_dst[e];
    int slot = atomicAdd(&g_pos[d], 1);
    g_csr[slot] = g_src[e];
}

// ---------------------------------------------------------------------------
// Layer-1 aggregation: warp per node; lanes = 4 neighbor-slots x 8 channel
// slots. One LDG.32 per lane per step -> 1 sector per neighbor row.
// ---------------------------------------------------------------------------
__global__ void agg1_kernel(int N) {
    int gt = blockIdx.x * blockDim.x + threadIdx.x;
    int n = gt >> 5, lane = gt & 31;
    if (n >= N) return;
    int off = g_off[n], deg = g_deg[n];
    int q = lane >> 3, r = lane & 7;
    const uint32_t* __restrict__ csr = (const uint32_t*)(g_csr + off);
    float ax = 0.f, ay = 0.f;
    int j = 0;
#pragma unroll 2
    for (; j + 4 <= deg; j += 4) {
        int s = csr[j + q];
        uint32_t u = __ldg(&g_xh[(size_t)s * 8 + r]);
        float2 f = __half22float2(*(__half2*)&u);
        ax += f.x; ay += f.y;
    }
    if (j + q < deg) {
        int s = csr[j + q];
        uint32_t u = __ldg(&g_xh[(size_t)s * 8 + r]);
        float2 f = __half22float2(*(__half2*)&u);
        ax += f.x; ay += f.y;
    }
    ax += __shfl_xor_sync(0xffffffffu, ax, 8);
    ay += __shfl_xor_sync(0xffffffffu, ay, 8);
    ax += __shfl_xor_sync(0xffffffffu, ax, 16);
    ay += __shfl_xor_sync(0xffffffffu, ay, 16);
    float inv = 1.0f / fmaxf((float)deg, 1.0f);
    if (lane < 6)
        ((float2*)g_agg1)[(size_t)n * 6 + lane] = make_float2(ax * inv, ay * inv);
}

// ---------------------------------------------------------------------------
// Layer-1 node pass v2: weights live in REGISTERS (22/thread), activations
// staged in smem and read as pure warp-broadcast LDS. 128 nodes per block.
// 256 threads = 64 channels x 4 node-slots.
// ---------------------------------------------------------------------------
__global__ void node1_kernel(const float* __restrict__ x,
                             const float* __restrict__ Wl1,
                             const float* __restrict__ bl1,
                             const float* __restrict__ Wr1, int N) {
    __shared__ float sM[128 * 12];
    __shared__ float sX[128 * 12];
    int tid = threadIdx.x;
    int n0 = blockIdx.x * 128;
    // stage means: 128 rows x 3 float4 (g_agg1 rows are 48B, 16B-aligned)
    for (int idx = tid; idx < 512; idx += 256) {
        int n = idx >> 2, f = idx & 3;
        if (f < 3) {
            float4 v = make_float4(0.f, 0.f, 0.f, 0.f);
            if (n0 + n < N) v = ((const float4*)g_agg1)[(size_t)(n0 + n) * 3 + f];
            ((float4*)sM)[n * 3 + f] = v;
        }
    }
    // stage x: fully coalesced scalar copy of 128*11 floats
    int xbase = n0 * 11;
    for (int idx = tid; idx < 128 * 11; idx += 256) {
        float v = (xbase + idx < N * 11) ? x[xbase + idx] : 0.f;
        int n = idx / 11, k = idx - n * 11;
        sX[n * 12 + k] = v;
    }
    __syncthreads();
    int c = tid & 63, s = tid >> 6;
    float wl[11], wr[11];
#pragma unroll
    for (int k = 0; k < 11; k++) {
        wl[k] = __ldg(Wl1 + c * 11 + k);
        wr[k] = __ldg(Wr1 + c * 11 + k);
    }
    float b = __ldg(bl1 + c);
    for (int n = s; n < 128; n += 4) {
        int gn = n0 + n;
        if (gn >= N) break;                      // uniform per warp
        float acc = b;
#pragma unroll
        for (int k = 0; k < 11; k++)
            acc += wl[k] * sM[n * 12 + k] + wr[k] * sX[n * 12 + k];
        float r = fmaxf(acc, 0.0f);
        g_h1[(size_t)gn * 64 + c] = r;
        float rn = __shfl_down_sync(0xffffffffu, r, 1);
        if (!(c & 1))
            g_h1h[(size_t)gn * 32 + (c >> 1)] = __floats2half2_rn(r, rn);
    }
}

// ---------------------------------------------------------------------------
// Layer-2 aggregation: warp per node, lane holds channels (2l, 2l+1).
// fp16 rows (128B = 4 sectors), unroll x8 for MLP. Atomic-free.
// ---------------------------------------------------------------------------
__global__ void agg2_kernel(int N) {
    int gt = blockIdx.x * blockDim.x + threadIdx.x;
    int n = gt >> 5, lane = gt & 31;
    if (n >= N) return;
    int off = g_off[n], deg = g_deg[n];
    const __half2* h1 = g_h1h;
    const int* __restrict__ csr = g_csr + off;
    float ax = 0.f, ay = 0.f;
    int j = 0;
    for (; j + 8 <= deg; j += 8) {
        int s0 = csr[j + 0], s1 = csr[j + 1], s2 = csr[j + 2], s3 = csr[j + 3];
        int s4 = csr[j + 4], s5 = csr[j + 5], s6 = csr[j + 6], s7 = csr[j + 7];
        __half2 v0 = __ldg(&h1[(size_t)s0 * 32 + lane]);
        __half2 v1 = __ldg(&h1[(size_t)s1 * 32 + lane]);
        __half2 v2 = __ldg(&h1[(size_t)s2 * 32 + lane]);
        __half2 v3 = __ldg(&h1[(size_t)s3 * 32 + lane]);
        __half2 v4 = __ldg(&h1[(size_t)s4 * 32 + lane]);
        __half2 v5 = __ldg(&h1[(size_t)s5 * 32 + lane]);
        __half2 v6 = __ldg(&h1[(size_t)s6 * 32 + lane]);
        __half2 v7 = __ldg(&h1[(size_t)s7 * 32 + lane]);
        float2 f0 = __half22float2(v0), f1 = __half22float2(v1);
        float2 f2 = __half22float2(v2), f3 = __half22float2(v3);
        float2 f4 = __half22float2(v4), f5 = __half22float2(v5);
        float2 f6 = __half22float2(v6), f7 = __half22float2(v7);
        ax += (f0.x + f1.x) + (f2.x + f3.x) + (f4.x + f5.x) + (f6.x + f7.x);
        ay += (f0.y + f1.y) + (f2.y + f3.y) + (f4.y + f5.y) + (f6.y + f7.y);
    }
    for (; j < deg; j++) {
        int s = csr[j];
        float2 f = __half22float2(__ldg(&h1[(size_t)s * 32 + lane]));
        ax += f.x; ay += f.y;
    }
    float inv = 1.0f / fmaxf((float)deg, 1.0f);
    ((float2*)g_agg2)[(size_t)n * 32 + lane] = make_float2(ax * inv, ay * inv);
}

// ---------------------------------------------------------------------------
// Layer-2 node pass v2: register-tiled GEMM + fused final linear.
// Block = 128 threads = 16 channel-tiles x 8 node-tiles; thread tile 4x4.
// sW[c][128] = [Wl2row | Wr2row], sA[n][128] = [mean2 | h1], both stored as
// 32 float4-groups per row with XOR swizzle grp ^= (row>>2)&7 so every
// LDS.128 in the k-loop is a 2-phase (minimum) access.
// ---------------------------------------------------------------------------
__global__ void node2_kernel(const float* __restrict__ Wl2,
                             const float* __restrict__ bl2,
                             const float* __restrict__ Wr2,
                             const float* __restrict__ Wlin,
                             const float* __restrict__ blin,
                             float* __restrict__ out, int N) {
    __shared__ float sW[64 * 128];   // 32 KB
    __shared__ float sA[32 * 128];   // 16 KB
    int tid = threadIdx.x;
    int n0 = blockIdx.x * 32;
    float4* Wp = (float4*)sW;
    float4* Ap = (float4*)sA;
    // stage weights: 64 rows x (16 grp Wl2 + 16 grp Wr2)
    for (int idx = tid; idx < 1024; idx += 128) {
        int c = idx >> 4, f = idx & 15;
        int sz = (c >> 2) & 7;
        Wp[c * 32 + (f ^ sz)] = ((const float4*)Wl2)[idx];
        Wp[c * 32 + ((16 + f) ^ sz)] = ((const float4*)Wr2)[idx];
    }
    // stage activations: 32 rows x (16 grp mean2 + 16 grp h1)
    for (int idx = tid; idx < 512; idx += 128) {
        int n = idx >> 4, f = idx & 15;
        int sz = (n >> 2) & 7;
        float4 vm = make_float4(0.f, 0.f, 0.f, 0.f);
        float4 vh = vm;
        if (n0 + n < N) {
            vm = ((const float4*)(g_agg2 + (size_t)(n0 + n) * 64))[f];
            vh = ((const float4*)(g_h1 + (size_t)(n0 + n) * 64))[f];
        }
        Ap[n * 32 + (f ^ sz)] = vm;
        Ap[n * 32 + ((16 + f) ^ sz)] = vh;
    }
    __syncthreads();

    int cx = tid & 15, ny = tid >> 4;   // ny in 0..7
    float acc[4][4];
#pragma unroll
    for (int i = 0; i < 4; i++)
#pragma unroll
        for (int j = 0; j < 4; j++) acc[i][j] = 0.f;

    int swz_w = cx & 7;
#pragma unroll 4
    for (int kk = 0; kk < 32; kk++) {
        int gw = kk ^ swz_w;
        int ga = kk ^ ny;
        float4 w0 = Wp[(4 * cx + 0) * 32 + gw];
        float4 w1 = Wp[(4 * cx + 1) * 32 + gw];
        float4 w2 = Wp[(4 * cx + 2) * 32 + gw];
        float4 w3 = Wp[(4 * cx + 3) * 32 + gw];
        float4 a0 = Ap[(4 * ny + 0) * 32 + ga];
        float4 a1 = Ap[(4 * ny + 1) * 32 + ga];
        float4 a2 = Ap[(4 * ny + 2) * 32 + ga];
        float4 a3 = Ap[(4 * ny + 3) * 32 + ga];
        const float4 w[4] = {w0, w1, w2, w3};
        const float4 a[4] = {a0, a1, a2, a3};
#pragma unroll
        for (int i = 0; i < 4; i++)
#pragma unroll
            for (int j = 0; j < 4; j++) {
                acc[i][j] += w[i].x * a[j].x + w[i].y * a[j].y
                           + w[i].z * a[j].z + w[i].w * a[j].w;
            }
    }

    // epilogue: relu + bias, dot with Wlin, reduce across the 16 cx-lanes
    float b4[4], wo4[4];
#pragma unroll
    for (int i = 0; i < 4; i++) {
        b4[i] = __ldg(bl2 + 4 * cx + i);
        wo4[i] = __ldg(Wlin + 4 * cx + i);
    }
    float bo = __ldg(blin);
#pragma unroll
    for (int j = 0; j < 4; j++) {
        float s = 0.f;
#pragma unroll
        for (int i = 0; i < 4; i++)
            s += wo4[i] * fmaxf(acc[i][j] + b4[i], 0.0f);
        s += __shfl_xor_sync(0xffffffffu, s, 1);
        s += __shfl_xor_sync(0xffffffffu, s, 2);
        s += __shfl_xor_sync(0xffffffffu, s, 4);
        s += __shfl_xor_sync(0xffffffffu, s, 8);
        int gn = n0 + 4 * ny + j;
        if (cx == 0 && gn < N) out[gn] = s + bo;
    }
}

// ---------------------------------------------------------------------------
extern "C" void kernel_launch(void* const* d_in, const int* in_sizes, int n_in,
                              void* d_out, int out_size) {
    const float* x    = (const float*)d_in[0];
    const void*  ei   = d_in[1];
    const float* Wl1  = (const float*)d_in[2];
    const float* bl1  = (const float*)d_in[3];
    const float* Wr1  = (const float*)d_in[4];
    const float* Wl2  = (const float*)d_in[5];
    const float* bl2  = (const float*)d_in[6];
    const float* Wr2  = (const float*)d_in[7];
    const float* Wlin = (const float*)d_in[8];
    const float* blin = (const float*)d_in[9];
    float* out = (float*)d_out;

    int N = in_sizes[0] / INC;
    int E = in_sizes[1] / 2;
    int nb = (N + 1023) / 1024;

    prep_kernel<<<(N + 255) / 256, 256>>>(ei, x, N);
    convert_kernel<<<(E + 255) / 256, 256>>>(ei, E);
    scan1_kernel<<<nb, 1024>>>(N);
    scan2_kernel<<<1, 256>>>(nb);
    scan3_kernel<<<(N + 255) / 256, 256>>>(N);
    build_kernel<<<(E + 255) / 256, 256>>>(E);

    long long t1 = (long long)N * 32;
    agg1_kernel<<<(int)((t1 + 255) / 256), 256>>>(N);
    node1_kernel<<<(N + 127) / 128, 256>>>(x, Wl1, bl1, Wr1, N);
    agg2_kernel<<<(int)((t1 + 255) / 256), 256>>>(N);
    node2_kernel<<<(N + 31) / 32, 128>>>(Wl2, bl2, Wr2, Wlin, blin, out, N);
}